// round 11
// baseline (speedup 1.0000x reference)
#include <cuda_runtime.h>
#include <cuda_bf16.h>
#include <cstdint>

#define DINL __device__ __forceinline__

// B=512, D=256, O=256, H=[512,1024,1024]
// out[b,o] = b_b[o] + sum_h x3[b,h]*W_b[o,h] + sum_d iv[b,d]*b_d[d*256+o]
//          + sum_{d,h} iv[b,d]*x3[b,h]*W_d[d*256+o, h]
// Main + comp_b via bf16 mma.sync, hi/lo 3-GEMM split.
// A (=iv*x3) staged in smem; B fragments LDG'd directly from fp32 W rows
// and split to bf16 hi/lo in registers (no smem round-trip for B).

__device__ float g_x1[512 * 512];
__device__ float g_x2[512 * 1024];
__device__ float g_x3[512 * 1024];
__device__ float g_part[16 * 512 * 256];   // split-K partials [z][b][o]

DINL uint32_t s2u(const void* p) {
    uint32_t a;
    asm("{ .reg .u64 t; cvta.to.shared.u64 t, %1; cvt.u32.u64 %0, t; }"
        : "=r"(a) : "l"(p));
    return a;
}
// pack: low half = bf16(e0), high half = bf16(e1)
DINL uint32_t bfpack(float e0, float e1) {
    uint32_t r;
    asm("cvt.rn.bf16x2.f32 %0, %1, %2;" : "=r"(r) : "f"(e1), "f"(e0));
    return r;
}
DINL void ldsm4(uint32_t* r, uint32_t a) {
    asm volatile("ldmatrix.sync.aligned.m8n8.x4.shared.b16 {%0,%1,%2,%3}, [%4];"
                 : "=r"(r[0]), "=r"(r[1]), "=r"(r[2]), "=r"(r[3]) : "r"(a));
}
DINL void mma16816(float* c, const uint32_t* a, const uint32_t* b) {
    asm volatile(
        "mma.sync.aligned.m16n8k16.row.col.f32.bf16.bf16.f32 "
        "{%0,%1,%2,%3}, {%4,%5,%6,%7}, {%8,%9}, {%0,%1,%2,%3};"
        : "+f"(c[0]), "+f"(c[1]), "+f"(c[2]), "+f"(c[3])
        : "r"(a[0]), "r"(a[1]), "r"(a[2]), "r"(a[3]), "r"(b[0]), "r"(b[1]));
}
// split fp32 pair -> bf16x2 hi + bf16x2 lo residual
DINL void split2(float f0, float f1, uint32_t& h, uint32_t& l) {
    h = bfpack(f0, f1);
    l = bfpack(f0 - __uint_as_float(h << 16),
               f1 - __uint_as_float(h & 0xFFFF0000u));
}
// split 8 fp32 -> bf16 hi (uint4) + bf16 lo residual (uint4)
DINL void split8(float4 f0, float4 f1, uint4& hi, uint4& lo) {
    split2(f0.x, f0.y, hi.x, lo.x);
    split2(f0.z, f0.w, hi.y, lo.y);
    split2(f1.x, f1.y, hi.z, lo.z);
    split2(f1.z, f1.w, hi.w, lo.w);
}

// A smem: double buffer, per buffer Ahi[128 x 16] + Alo[128 x 16], stride 24
static constexpr int RST = 24;
static constexpr int A_TILE = 128 * RST;     // 3072 el
static constexpr int A_BUF = 2 * A_TILE;     // hi + lo = 6144 el (12 KB)

// ---------------------------------------------------------------------------
// Main contraction. Grid (m=4, n=2, z=16), 256 threads = 8 warps.
// Warp tile 64x32 (wm = (wid>>2)*64, wn = (wid&3)*32).
// K per CTA = 16*1024 (+1024 Wb fold at z==0), stages of K=16.
// ---------------------------------------------------------------------------
__global__ __launch_bounds__(256, 1) void main_mma_kernel(
    const float* __restrict__ iv, const float* __restrict__ Wd,
    const float* __restrict__ Wb, const float* __restrict__ x3)
{
    __shared__ __align__(16) __nv_bfloat16 smA[2][A_BUF];

    const int tid = threadIdx.x, lane = tid & 31, wid = tid >> 5;
    const int m0 = blockIdx.x * 128, n0 = blockIdx.y * 128, z = blockIdx.z;
    const int nst = ((z == 0) ? 17 : 16) * 64;
    const int wm = (wid >> 2) * 64, wn = (wid & 3) * 32;

    // ---- A production role: thread t -> row tid>>1, k-half (tid&1)*8 ----
    const int prow = tid >> 1, pkh = (tid & 1) * 8;
    float4 aP0, aP1;           // A(s) fp32, iv-premultiplied
    auto ldgA = [&](int s) {
        int g = s >> 6, h0 = (s & 63) * 16;
        float ivv;
        const float* xp = x3 + (size_t)(m0 + prow) * 1024 + h0 + pkh;
        if (g < 16) ivv = __ldg(iv + (size_t)(m0 + prow) * 256 + (z * 16 + g));
        else        ivv = 1.0f;
        aP0 = *(const float4*)xp; aP1 = *(const float4*)(xp + 4);
        aP0.x *= ivv; aP0.y *= ivv; aP0.z *= ivv; aP0.w *= ivv;
        aP1.x *= ivv; aP1.y *= ivv; aP1.z *= ivv; aP1.w *= ivv;
    };
    auto stsA = [&](int buf) {
        uint4 hi, lo;
        split8(aP0, aP1, hi, lo);
        __nv_bfloat16* bp = &smA[buf][prow * RST + pkh];
        *(uint4*)bp = hi;
        *(uint4*)(bp + A_TILE) = lo;
    };

    // ---- B fragment LDG: 4 n8-frags, lane l: n = l>>2, k = 2*(l&3) ----
    float4 bP[4];              // {k0, k0+1, k0+8, k0+9} per frag
    const int bn = lane >> 2, bk = (lane & 3) * 2;
    auto ldgB = [&](int s) {
        int g = s >> 6, h0 = (s & 63) * 16;
        const float* Wbase = (g < 16) ? (Wd + (size_t)(z * 16 + g) * 256 * 1024) : Wb;
        #pragma unroll
        for (int f = 0; f < 4; f++) {
            const float* p = Wbase + (size_t)(n0 + wn + f * 8 + bn) * 1024 + h0 + bk;
            float2 lo2 = *(const float2*)p;
            float2 hi2 = *(const float2*)(p + 8);
            bP[f] = make_float4(lo2.x, lo2.y, hi2.x, hi2.y);
        }
    };

    // ---- A fragment ldmatrix addressing ----
    const int arow = (lane & 7) + ((lane >> 3) & 1) * 8;
    const int akh = ((lane >> 4) & 1) * 8;
    uint32_t aoffh[4], aoffl[4];
    {
        const uint32_t smu = s2u(smA);
        #pragma unroll
        for (int t = 0; t < 4; t++) {
            int e = (wm + t * 16 + arow) * RST + akh;
            aoffh[t] = smu + (uint32_t)e * 2;
            aoffl[t] = smu + (uint32_t)(e + A_TILE) * 2;
        }
    }

    float acc[4][4][4] = {};   // [m16 tile][n8 frag][c-frag]
    uint32_t Ah[4][4], Al[4][4], Bh[4][2], Bl[4][2];

    // ---- prologue ----
    ldgA(0); ldgB(0);
    stsA(0);
    ldgA(1);
    __syncthreads();

    const int last = nst - 1;
    for (int s = 0; s < nst; ++s) {
        const int buf = s & 1;
        const int sB = (s < last) ? s + 1 : last;       // B prefetch index
        const int sA = (s + 2 <= last) ? s + 2 : last;  // A prefetch index

        // convert B(s) fp32 -> bf16 hi/lo fragments (frees bP for prefetch)
        #pragma unroll
        for (int f = 0; f < 4; f++) {
            split2(bP[f].x, bP[f].y, Bh[f][0], Bl[f][0]);
            split2(bP[f].z, bP[f].w, Bh[f][1], Bl[f][1]);
        }
        // stage A(s+1) into the other buffer (aP holds A(s+1))
        stsA(buf ^ 1);
        // prefetch B(s+1), A(s+2)
        ldgB(sB);
        ldgA(sA);

        // A fragments for stage s
        const uint32_t bofs = (uint32_t)buf * (A_BUF * 2);
        #pragma unroll
        for (int t = 0; t < 4; t++) ldsm4(Ah[t], aoffh[t] + bofs);
        #pragma unroll
        for (int t = 0; t < 4; t++) ldsm4(Al[t], aoffl[t] + bofs);

        // 48 MMAs, term-major (same-acc reuse 16 apart)
        #pragma unroll
        for (int t = 0; t < 4; t++)
            #pragma unroll
            for (int f = 0; f < 4; f++) mma16816(acc[t][f], Ah[t], Bh[f]);
        #pragma unroll
        for (int t = 0; t < 4; t++)
            #pragma unroll
            for (int f = 0; f < 4; f++) mma16816(acc[t][f], Al[t], Bh[f]);
        #pragma unroll
        for (int t = 0; t < 4; t++)
            #pragma unroll
            for (int f = 0; f < 4; f++) mma16816(acc[t][f], Ah[t], Bl[f]);

        __syncthreads();
    }

    // ---- epilogue: split-K partials ----
    float* part = g_part + (size_t)z * (512 * 256);
    #pragma unroll
    for (int t = 0; t < 4; t++) {
        int mr = m0 + wm + t * 16 + (lane >> 2);
        #pragma unroll
        for (int f = 0; f < 4; f++) {
            int nc = n0 + wn + f * 8 + (lane & 3) * 2;
            *(float2*)(part + (size_t)mr * 256 + nc) =
                make_float2(acc[t][f][0], acc[t][f][1]);
            *(float2*)(part + (size_t)(mr + 8) * 256 + nc) =
                make_float2(acc[t][f][2], acc[t][f][3]);
        }
    }
}

// ---------------------------------------------------------------------------
// MLP layer: C = relu(A @ W^T + bias)   (fp32 SIMT)
// ---------------------------------------------------------------------------
__global__ __launch_bounds__(256) void mlp_layer_kernel(
    const float* __restrict__ A, const float* __restrict__ W,
    const float* __restrict__ bias, float* __restrict__ C,
    int M, int N, int K)
{
    __shared__ float a_s[16][68];
    __shared__ float w_s[16][68];
    int m0 = blockIdx.y * 64, n0 = blockIdx.x * 64;
    int tid = threadIdx.x;
    int tx = tid & 15, ty = tid >> 4;
    int lrow = tid >> 2, lk = (tid & 3) * 4;
    float acc[4][4] = {};

    for (int k0 = 0; k0 < K; k0 += 16) {
        float4 av = *(const float4*)(A + (size_t)(m0 + lrow) * K + k0 + lk);
        float4 wv = *(const float4*)(W + (size_t)(n0 + lrow) * K + k0 + lk);
        a_s[lk + 0][lrow] = av.x; a_s[lk + 1][lrow] = av.y;
        a_s[lk + 2][lrow] = av.z; a_s[lk + 3][lrow] = av.w;
        w_s[lk + 0][lrow] = wv.x; w_s[lk + 1][lrow] = wv.y;
        w_s[lk + 2][lrow] = wv.z; w_s[lk + 3][lrow] = wv.w;
        __syncthreads();
        #pragma unroll
        for (int kk = 0; kk < 16; kk++) {
            float4 ra = *(const float4*)&a_s[kk][ty * 4];
            float4 rb = *(const float4*)&w_s[kk][tx * 4];
            float ar[4] = {ra.x, ra.y, ra.z, ra.w};
            float br[4] = {rb.x, rb.y, rb.z, rb.w};
            #pragma unroll
            for (int i = 0; i < 4; i++)
                #pragma unroll
                for (int j = 0; j < 4; j++)
                    acc[i][j] += ar[i] * br[j];
        }
        __syncthreads();
    }
    #pragma unroll
    for (int i = 0; i < 4; i++) {
        int m = m0 + ty * 4 + i;
        #pragma unroll
        for (int j = 0; j < 4; j++) {
            int n = n0 + tx * 4 + j;
            float v = acc[i][j] + bias[n];
            C[(size_t)m * N + n] = v > 0.f ? v : 0.f;
        }
    }
}

// ---------------------------------------------------------------------------
// out[b,o] = b_b[o] + sum_z part[z][b,o] + sum_d iv[b,d]*b_d[d*256+o]
// ---------------------------------------------------------------------------
__global__ __launch_bounds__(256) void reduce_kernel(
    const float* __restrict__ iv, const float* __restrict__ bd,
    const float* __restrict__ bb, float* __restrict__ out)
{
    __shared__ float sIv[256];
    int b = blockIdx.x;
    int o = threadIdx.x;
    sIv[o] = iv[(size_t)b * 256 + o];
    __syncthreads();
    size_t idx = (size_t)b * 256 + o;
    float s = bb[o];
    #pragma unroll 8
    for (int z = 0; z < 16; z++)
        s += g_part[(size_t)z * 131072 + idx];
    #pragma unroll 8
    for (int d = 0; d < 256; d++)
        s = fmaf(sIv[d], bd[d * 256 + o], s);
    out[idx] = s;
}

extern "C" void kernel_launch(void* const* d_in, const int* in_sizes, int n_in,
                              void* d_out, int out_size)
{
    const float* IV = (const float*)d_in[0];   // input_values [512,256]
    const float* NF = (const float*)d_in[1];   // nan_flag     [512,256]
    int base = (in_sizes[2] == 512 * 256) ? 2 : 3;   // skip `training` if present
    const float* W_in = (const float*)d_in[base + 0];  // [512,256]
    const float* b_in = (const float*)d_in[base + 1];  // [512]
    const float* W_h1 = (const float*)d_in[base + 2];  // [1024,512]
    const float* b_h1 = (const float*)d_in[base + 3];  // [1024]
    const float* W_h2 = (const float*)d_in[base + 4];  // [1024,1024]
    const float* b_h2 = (const float*)d_in[base + 5];  // [1024]
    const float* W_d  = (const float*)d_in[base + 6];  // [65536,1024]
    const float* b_d  = (const float*)d_in[base + 7];  // [65536]
    const float* W_b  = (const float*)d_in[base + 8];  // [256,1024]
    const float* b_b  = (const float*)d_in[base + 9];  // [256]
    float* out = (float*)d_out;

    float *x1, *x2, *x3;
    cudaGetSymbolAddress((void**)&x1, g_x1);
    cudaGetSymbolAddress((void**)&x2, g_x2);
    cudaGetSymbolAddress((void**)&x3, g_x3);

    // MLP
    mlp_layer_kernel<<<dim3(8, 8), 256>>>(NF, W_in, b_in, x1, 512, 512, 256);
    mlp_layer_kernel<<<dim3(16, 8), 256>>>(x1, W_h1, b_h1, x2, 512, 1024, 512);
    mlp_layer_kernel<<<dim3(16, 8), 256>>>(x2, W_h2, b_h2, x3, 512, 1024, 1024);

    // Main contraction (+ W_b fold at z==0): B direct-LDG, A via smem
    main_mma_kernel<<<dim3(4, 2, 16), 256>>>(IV, W_d, W_b, x3);

    // Deterministic split-K reduce + bias terms
    reduce_kernel<<<dim3(512), 256>>>(IV, b_d, b_b, out);
}

// round 12
// speedup vs baseline: 1.1161x; 1.1161x over previous
#include <cuda_runtime.h>
#include <cuda_bf16.h>
#include <cstdint>

#define DINL __device__ __forceinline__

// B=512, D=256, O=256, H=[512,1024,1024]
// out[b,o] = b_b[o] + sum_h x3[b,h]*W_b[o,h] + sum_d iv[b,d]*b_d[d*256+o]
//          + sum_{d,h} iv[b,d]*x3[b,h]*W_d[d*256+o, h]
// Main + comp_b via bf16 mma.sync (hi/lo 3-GEMM split), split-K over d.
// R6 structure with rotated software pipeline: STS uses regs LDG'd one full
// iteration earlier, so the gmem latency is covered by a whole MMA stage.

__device__ float g_x1[512 * 512];
__device__ float g_x2[512 * 1024];
__device__ float g_x3[512 * 1024];
__device__ float g_part[32 * 512 * 256];   // split-K partials [z][b][o]

DINL uint32_t s2u(const void* p) {
    uint32_t a;
    asm("{ .reg .u64 t; cvta.to.shared.u64 t, %1; cvt.u32.u64 %0, t; }"
        : "=r"(a) : "l"(p));
    return a;
}
// pack: low half = bf16(e0), high half = bf16(e1)
DINL uint32_t bfpack(float e0, float e1) {
    uint32_t r;
    asm("cvt.rn.bf16x2.f32 %0, %1, %2;" : "=r"(r) : "f"(e1), "f"(e0));
    return r;
}
DINL void ldsm4(uint32_t* r, uint32_t a) {
    asm volatile("ldmatrix.sync.aligned.m8n8.x4.shared.b16 {%0,%1,%2,%3}, [%4];"
                 : "=r"(r[0]), "=r"(r[1]), "=r"(r[2]), "=r"(r[3]) : "r"(a));
}
DINL void mma16816(float* c, const uint32_t* a, const uint32_t* b) {
    asm volatile(
        "mma.sync.aligned.m16n8k16.row.col.f32.bf16.bf16.f32 "
        "{%0,%1,%2,%3}, {%4,%5,%6,%7}, {%8,%9}, {%0,%1,%2,%3};"
        : "+f"(c[0]), "+f"(c[1]), "+f"(c[2]), "+f"(c[3])
        : "r"(a[0]), "r"(a[1]), "r"(a[2]), "r"(a[3]), "r"(b[0]), "r"(b[1]));
}

// smem layout (bf16 elements), row stride 24 (48B: ldmatrix conflict-free)
static constexpr int AS = 128 * 24;              // A tile (128 rows x 16 k)
static constexpr int BS = 256 * 24;              // B tile (256 rows x 16 k)
static constexpr int BUF_EL = 2 * AS + 2 * BS;   // Ahi|Alo|Bhi|Blo = 18432 el
static constexpr int OAHI = 0, OALO = AS, OBHI = 2 * AS, OBLO = 2 * AS + BS;
static constexpr int BUF_BYTES = BUF_EL * 2;     // 36864 B
static constexpr int DSMEM_BYTES = 2 * BUF_BYTES;   // 73728 B

// ---------------------------------------------------------------------------
// Main fused contraction on warp MMA. Grid (m=4, z=32), 512 threads.
// CTA output tile 128x256 fp32 in regs; K = 8*1024 (+1024 Wb fold at z==0).
// ---------------------------------------------------------------------------
__global__ __launch_bounds__(512, 1) void main_mma_kernel(
    const float* __restrict__ iv, const float* __restrict__ Wd,
    const float* __restrict__ Wb, const float* __restrict__ x3)
{
    extern __shared__ __align__(16) __nv_bfloat16 sm[];
    const int tid = threadIdx.x, lane = tid & 31, wid = tid >> 5;
    const int m0 = blockIdx.x * 128, z = blockIdx.y;
    const int wm = (wid & 1) * 64, wn = (wid >> 1) * 32;
    const int nst = (z == 0) ? 9 * 64 : 8 * 64;

    // load roles: A-gen 4 threads/row (4 el), B 2 threads/row (8 el)
    const int rowA = tid >> 2, k4 = (tid & 3) * 4;
    const int rowB = tid >> 1, k8 = (tid & 1) * 8;

    float acc[4][4][4] = {};   // [mi][ni][frag]

    float4 aF, b0F, b1F;
    float ivv;
    auto ldg_stage = [&](int s) {
        int g = s >> 6, h0 = (s & 63) * 16;
        const float* Wbase = (g < 8) ? (Wd + ((size_t)((z * 8 + g) * 256)) * 1024) : Wb;
        ivv = (g < 8) ? __ldg(iv + (size_t)(m0 + rowA) * 256 + (z * 8 + g)) : 1.0f;
        aF = *(const float4*)(x3 + (size_t)(m0 + rowA) * 1024 + h0 + k4);
        const float* wp = Wbase + (size_t)rowB * 1024 + h0 + k8;
        b0F = *(const float4*)(wp);
        b1F = *(const float4*)(wp + 4);
    };

    // convert + STS from current regs into buffer `buf`
    auto sts_stage = [&](int buf) {
        __nv_bfloat16* bp = sm + buf * BUF_EL;
        float fx = aF.x * ivv, fy = aF.y * ivv, fz = aF.z * ivv, fw = aF.w * ivv;
        uint32_t h01 = bfpack(fx, fy), h23 = bfpack(fz, fw);
        float hx = __uint_as_float(h01 << 16);
        float hy = __uint_as_float(h01 & 0xFFFF0000u);
        float hz = __uint_as_float(h23 << 16);
        float hw = __uint_as_float(h23 & 0xFFFF0000u);
        uint32_t l01 = bfpack(fx - hx, fy - hy), l23 = bfpack(fz - hz, fw - hw);
        *(uint2*)(bp + OAHI + rowA * 24 + k4) = make_uint2(h01, h23);
        *(uint2*)(bp + OALO + rowA * 24 + k4) = make_uint2(l01, l23);

        uint32_t p01 = bfpack(b0F.x, b0F.y), p23 = bfpack(b0F.z, b0F.w);
        float px = __uint_as_float(p01 << 16);
        float py = __uint_as_float(p01 & 0xFFFF0000u);
        float pz = __uint_as_float(p23 << 16);
        float pw = __uint_as_float(p23 & 0xFFFF0000u);
        uint32_t q01 = bfpack(b0F.x - px, b0F.y - py);
        uint32_t q23 = bfpack(b0F.z - pz, b0F.w - pw);
        *(uint2*)(bp + OBHI + rowB * 24 + k8) = make_uint2(p01, p23);
        *(uint2*)(bp + OBLO + rowB * 24 + k8) = make_uint2(q01, q23);

        uint32_t r01 = bfpack(b1F.x, b1F.y), r23 = bfpack(b1F.z, b1F.w);
        float rx = __uint_as_float(r01 << 16);
        float ry = __uint_as_float(r01 & 0xFFFF0000u);
        float rz = __uint_as_float(r23 << 16);
        float rw = __uint_as_float(r23 & 0xFFFF0000u);
        uint32_t s01 = bfpack(b1F.x - rx, b1F.y - ry);
        uint32_t s23 = bfpack(b1F.z - rz, b1F.w - rw);
        *(uint2*)(bp + OBHI + rowB * 24 + k8 + 4) = make_uint2(r01, r23);
        *(uint2*)(bp + OBLO + rowB * 24 + k8 + 4) = make_uint2(s01, s23);
    };

    const uint32_t smu = s2u(sm);
    // ldmatrix per-lane addresses (element offsets within a tile)
    const int arow = (lane & 7) + ((lane >> 3) & 1) * 8;
    const int akh = ((lane >> 4) & 1) * 8;
    const int brow = (lane & 7) + ((lane >> 4) & 1) * 8;
    const int bkh = ((lane >> 3) & 1) * 8;

    // ---- prologue: fill buf0 with stage 0; regs end holding stage 1 ----
    ldg_stage(0);
    sts_stage(0);
    ldg_stage(1);
    __syncthreads();

    const int last = nst - 1;
    for (int s = 0; s < nst; ++s) {
        const int buf = s & 1;

        // stage s+1 -> other buffer (regs loaded one full iteration ago)
        sts_stage(buf ^ 1);
        // prefetch stage s+2 (consumed at top of next iteration)
        ldg_stage(s + 2 <= last ? s + 2 : last);

        // ---- ldmatrix + 48 mma from current buffer ----
        const uint32_t base = smu + (uint32_t)buf * BUF_BYTES;
        uint32_t Ah[4][4], Bh[2][4], Bl[2][4];
        #pragma unroll
        for (int t = 0; t < 4; t++)
            ldsm4(Ah[t], base + (uint32_t)(OAHI + (wm + t * 16 + arow) * 24 + akh) * 2);
        #pragma unroll
        for (int p = 0; p < 2; p++) {
            ldsm4(Bh[p], base + (uint32_t)(OBHI + (wn + p * 16 + brow) * 24 + bkh) * 2);
            ldsm4(Bl[p], base + (uint32_t)(OBLO + (wn + p * 16 + brow) * 24 + bkh) * 2);
        }
        #pragma unroll
        for (int mi = 0; mi < 4; mi++)
            #pragma unroll
            for (int ni = 0; ni < 4; ni++) {
                mma16816(acc[mi][ni], Ah[mi], &Bh[ni >> 1][(ni & 1) * 2]);
                mma16816(acc[mi][ni], Ah[mi], &Bl[ni >> 1][(ni & 1) * 2]);
            }
        uint32_t Al[4][4];
        #pragma unroll
        for (int t = 0; t < 4; t++)
            ldsm4(Al[t], base + (uint32_t)(OALO + (wm + t * 16 + arow) * 24 + akh) * 2);
        #pragma unroll
        for (int mi = 0; mi < 4; mi++)
            #pragma unroll
            for (int ni = 0; ni < 4; ni++)
                mma16816(acc[mi][ni], Al[mi], &Bh[ni >> 1][(ni & 1) * 2]);

        __syncthreads();
    }

    // ---- epilogue: write split-K partials ----
    float* part = g_part + (size_t)z * (512 * 256);
    #pragma unroll
    for (int mi = 0; mi < 4; mi++) {
        int mr = m0 + wm + mi * 16 + (lane >> 2);
        #pragma unroll
        for (int ni = 0; ni < 4; ni++) {
            int nc = wn + ni * 8 + (lane & 3) * 2;
            *(float2*)(part + (size_t)mr * 256 + nc) =
                make_float2(acc[mi][ni][0], acc[mi][ni][1]);
            *(float2*)(part + (size_t)(mr + 8) * 256 + nc) =
                make_float2(acc[mi][ni][2], acc[mi][ni][3]);
        }
    }
}

// ---------------------------------------------------------------------------
// MLP layer: C = relu(A @ W^T + bias)   (fp32 SIMT; next-round target)
// ---------------------------------------------------------------------------
__global__ __launch_bounds__(256) void mlp_layer_kernel(
    const float* __restrict__ A, const float* __restrict__ W,
    const float* __restrict__ bias, float* __restrict__ C,
    int M, int N, int K)
{
    __shared__ float a_s[16][68];
    __shared__ float w_s[16][68];
    int m0 = blockIdx.y * 64, n0 = blockIdx.x * 64;
    int tid = threadIdx.x;
    int tx = tid & 15, ty = tid >> 4;
    int lrow = tid >> 2, lk = (tid & 3) * 4;
    float acc[4][4] = {};

    for (int k0 = 0; k0 < K; k0 += 16) {
        float4 av = *(const float4*)(A + (size_t)(m0 + lrow) * K + k0 + lk);
        float4 wv = *(const float4*)(W + (size_t)(n0 + lrow) * K + k0 + lk);
        a_s[lk + 0][lrow] = av.x; a_s[lk + 1][lrow] = av.y;
        a_s[lk + 2][lrow] = av.z; a_s[lk + 3][lrow] = av.w;
        w_s[lk + 0][lrow] = wv.x; w_s[lk + 1][lrow] = wv.y;
        w_s[lk + 2][lrow] = wv.z; w_s[lk + 3][lrow] = wv.w;
        __syncthreads();
        #pragma unroll
        for (int kk = 0; kk < 16; kk++) {
            float4 ra = *(const float4*)&a_s[kk][ty * 4];
            float4 rb = *(const float4*)&w_s[kk][tx * 4];
            float ar[4] = {ra.x, ra.y, ra.z, ra.w};
            float br[4] = {rb.x, rb.y, rb.z, rb.w};
            #pragma unroll
            for (int i = 0; i < 4; i++)
                #pragma unroll
                for (int j = 0; j < 4; j++)
                    acc[i][j] += ar[i] * br[j];
        }
        __syncthreads();
    }
    #pragma unroll
    for (int i = 0; i < 4; i++) {
        int m = m0 + ty * 4 + i;
        #pragma unroll
        for (int j = 0; j < 4; j++) {
            int n = n0 + tx * 4 + j;
            float v = acc[i][j] + bias[n];
            C[(size_t)m * N + n] = v > 0.f ? v : 0.f;
        }
    }
}

// ---------------------------------------------------------------------------
// out[b,o] = b_b[o] + sum_z part[z][b,o] + sum_d iv[b,d]*b_d[d*256+o]
// ---------------------------------------------------------------------------
__global__ __launch_bounds__(256) void reduce_kernel(
    const float* __restrict__ iv, const float* __restrict__ bd,
    const float* __restrict__ bb, float* __restrict__ out)
{
    __shared__ float sIv[256];
    int b = blockIdx.x;
    int o = threadIdx.x;
    sIv[o] = iv[(size_t)b * 256 + o];
    __syncthreads();
    size_t idx = (size_t)b * 256 + o;
    float s = bb[o];
    #pragma unroll 8
    for (int z = 0; z < 32; z++)
        s += g_part[(size_t)z * 131072 + idx];
    #pragma unroll 8
    for (int d = 0; d < 256; d++)
        s = fmaf(sIv[d], bd[d * 256 + o], s);
    out[idx] = s;
}

extern "C" void kernel_launch(void* const* d_in, const int* in_sizes, int n_in,
                              void* d_out, int out_size)
{
    const float* IV = (const float*)d_in[0];   // input_values [512,256]
    const float* NF = (const float*)d_in[1];   // nan_flag     [512,256]
    int base = (in_sizes[2] == 512 * 256) ? 2 : 3;   // skip `training` if present
    const float* W_in = (const float*)d_in[base + 0];  // [512,256]
    const float* b_in = (const float*)d_in[base + 1];  // [512]
    const float* W_h1 = (const float*)d_in[base + 2];  // [1024,512]
    const float* b_h1 = (const float*)d_in[base + 3];  // [1024]
    const float* W_h2 = (const float*)d_in[base + 4];  // [1024,1024]
    const float* b_h2 = (const float*)d_in[base + 5];  // [1024]
    const float* W_d  = (const float*)d_in[base + 6];  // [65536,1024]
    const float* b_d  = (const float*)d_in[base + 7];  // [65536]
    const float* W_b  = (const float*)d_in[base + 8];  // [256,1024]
    const float* b_b  = (const float*)d_in[base + 9];  // [256]
    float* out = (float*)d_out;

    float *x1, *x2, *x3;
    cudaGetSymbolAddress((void**)&x1, g_x1);
    cudaGetSymbolAddress((void**)&x2, g_x2);
    cudaGetSymbolAddress((void**)&x3, g_x3);

    cudaFuncSetAttribute(main_mma_kernel,
                         cudaFuncAttributeMaxDynamicSharedMemorySize, DSMEM_BYTES);

    // MLP
    mlp_layer_kernel<<<dim3(8, 8), 256>>>(NF, W_in, b_in, x1, 512, 512, 256);
    mlp_layer_kernel<<<dim3(16, 8), 256>>>(x1, W_h1, b_h1, x2, 512, 1024, 512);
    mlp_layer_kernel<<<dim3(16, 8), 256>>>(x2, W_h2, b_h2, x3, 512, 1024, 1024);

    // Main contraction (+ W_b fold at z==0), rotated pipeline
    main_mma_kernel<<<dim3(4, 32), 512, DSMEM_BYTES>>>(IV, W_d, W_b, x3);

    // Deterministic split-K reduce + bias terms
    reduce_kernel<<<dim3(512), 256>>>(IV, b_d, b_b, out);
}

// round 14
// speedup vs baseline: 1.2266x; 1.0990x over previous
#include <cuda_runtime.h>
#include <cuda_bf16.h>
#include <cstdint>

#define DINL __device__ __forceinline__

// B=512, D=256, O=256, H=[512,1024,1024]
// out[b,o] = b_b[o] + sum_h x3[b,h]*W_b[o,h] + sum_d iv[b,d]*b_d[d*256+o]
//          + sum_{d,h} iv[b,d]*x3[b,h]*W_d[d*256+o, h]
// Main + comp_b via bf16 mma.sync (hi/lo 3-GEMM split), split-K over d.
// R6 inner loop, retiled to 128x128 CTA / 256 threads so 2 CTAs co-reside
// per SM and cover each other's barrier/LDSM stalls.

__device__ float g_x1[512 * 512];
__device__ float g_x2[512 * 1024];
__device__ float g_x3[512 * 1024];
__device__ float g_part[32 * 512 * 256];   // split-K partials [z][b][o]

DINL uint32_t s2u(const void* p) {
    uint32_t a;
    asm("{ .reg .u64 t; cvta.to.shared.u64 t, %1; cvt.u32.u64 %0, t; }"
        : "=r"(a) : "l"(p));
    return a;
}
// pack: low half = bf16(e0), high half = bf16(e1)
DINL uint32_t bfpack(float e0, float e1) {
    uint32_t r;
    asm("cvt.rn.bf16x2.f32 %0, %1, %2;" : "=r"(r) : "f"(e1), "f"(e0));
    return r;
}
DINL void ldsm4(uint32_t* r, uint32_t a) {
    asm volatile("ldmatrix.sync.aligned.m8n8.x4.shared.b16 {%0,%1,%2,%3}, [%4];"
                 : "=r"(r[0]), "=r"(r[1]), "=r"(r[2]), "=r"(r[3]) : "r"(a));
}
DINL void mma16816(float* c, const uint32_t* a, const uint32_t* b) {
    asm volatile(
        "mma.sync.aligned.m16n8k16.row.col.f32.bf16.bf16.f32 "
        "{%0,%1,%2,%3}, {%4,%5,%6,%7}, {%8,%9}, {%0,%1,%2,%3};"
        : "+f"(c[0]), "+f"(c[1]), "+f"(c[2]), "+f"(c[3])
        : "r"(a[0]), "r"(a[1]), "r"(a[2]), "r"(a[3]), "r"(b[0]), "r"(b[1]));
}
// split 8 fp32 -> bf16 hi (uint4) + bf16 lo residual (uint4)
DINL void split8(float4 f0, float4 f1, uint4& hi, uint4& lo) {
    hi.x = bfpack(f0.x, f0.y); hi.y = bfpack(f0.z, f0.w);
    hi.z = bfpack(f1.x, f1.y); hi.w = bfpack(f1.z, f1.w);
    lo.x = bfpack(f0.x - __uint_as_float(hi.x << 16),
                  f0.y - __uint_as_float(hi.x & 0xFFFF0000u));
    lo.y = bfpack(f0.z - __uint_as_float(hi.y << 16),
                  f0.w - __uint_as_float(hi.y & 0xFFFF0000u));
    lo.z = bfpack(f1.x - __uint_as_float(hi.z << 16),
                  f1.y - __uint_as_float(hi.z & 0xFFFF0000u));
    lo.w = bfpack(f1.z - __uint_as_float(hi.w << 16),
                  f1.w - __uint_as_float(hi.w & 0xFFFF0000u));
}

// smem: per buffer Ahi|Alo|Bhi|Blo, each 128 rows x 16 k, row stride 24 el
static constexpr int RST = 24;
static constexpr int TS = 128 * RST;             // 3072 el per tile
static constexpr int OAHI = 0, OALO = TS, OBHI = 2 * TS, OBLO = 3 * TS;
static constexpr int BUF_EL = 4 * TS;            // 12288 el
static constexpr int BUF_BYTES = BUF_EL * 2;     // 24576 B
// static smem 2 buffers = 48 KB per CTA -> 2 CTAs/SM = 96 KB

// ---------------------------------------------------------------------------
// Main fused contraction. Grid (m=4, n=2, z=32), 256 threads = 8 warps.
// Warp tile 32x64 (wm=(wid>>1)*32, wn=(wid&1)*64).
// K per CTA = 8*1024 (+1024 Wb fold at z==0), stages of K=16.
// ---------------------------------------------------------------------------
__global__ __launch_bounds__(256, 2) void main_mma_kernel(
    const float* __restrict__ iv, const float* __restrict__ Wd,
    const float* __restrict__ Wb, const float* __restrict__ x3)
{
    __shared__ __align__(16) __nv_bfloat16 sm[2][BUF_EL];

    const int tid = threadIdx.x, lane = tid & 31, wid = tid >> 5;
    const int m0 = blockIdx.x * 128, n0 = blockIdx.y * 128, z = blockIdx.z;
    const int wm = (wid >> 1) * 32, wn = (wid & 1) * 64;
    const int nst = (z == 0) ? 9 * 64 : 8 * 64;

    // load role: 2 threads per row, 8 contiguous floats each
    const int row = tid >> 1, k8 = (tid & 1) * 8;

    float acc[2][8][4] = {};   // [m16 tile][n8 frag][c-frag]

    float4 aF0, aF1, bF0, bF1;
    float ivv;
    auto ldg_stage = [&](int s) {
        int g = s >> 6, h0 = (s & 63) * 16;
        const float* Wbase;
        if (g < 8) {
            Wbase = Wd + ((size_t)((z * 8 + g) * 256 + n0)) * 1024;
            ivv = __ldg(iv + (size_t)(m0 + row) * 256 + (z * 8 + g));
        } else {
            Wbase = Wb + (size_t)n0 * 1024;
            ivv = 1.0f;
        }
        const float* xp = x3 + (size_t)(m0 + row) * 1024 + h0 + k8;
        aF0 = *(const float4*)xp; aF1 = *(const float4*)(xp + 4);
        const float* wp = Wbase + (size_t)row * 1024 + h0 + k8;
        bF0 = *(const float4*)wp; bF1 = *(const float4*)(wp + 4);
    };

    const uint32_t smu = s2u(sm);
    // ldmatrix per-lane addresses (element offsets within a tile)
    const int arow = (lane & 7) + ((lane >> 3) & 1) * 8;
    const int akh = ((lane >> 4) & 1) * 8;
    const int brow = (lane & 7) + ((lane >> 4) & 1) * 8;
    const int bkh = ((lane >> 3) & 1) * 8;

    ldg_stage(0);

    const int last = nst - 1;
    const int rowoff = row * RST + k8;
    for (int s = 0; s < nst; ++s) {
        const int buf = s & 1;
        __nv_bfloat16* bp = sm[buf];

        // ---- convert + STS stage s (A = iv*x3; hi/lo bf16 split) ----
        {
            float4 a0 = aF0, a1 = aF1;
            a0.x *= ivv; a0.y *= ivv; a0.z *= ivv; a0.w *= ivv;
            a1.x *= ivv; a1.y *= ivv; a1.z *= ivv; a1.w *= ivv;
            uint4 hi, lo;
            split8(a0, a1, hi, lo);
            *(uint4*)(bp + OAHI + rowoff) = hi;
            *(uint4*)(bp + OALO + rowoff) = lo;
            split8(bF0, bF1, hi, lo);
            *(uint4*)(bp + OBHI + rowoff) = hi;
            *(uint4*)(bp + OBLO + rowoff) = lo;
        }
        __syncthreads();

        // prefetch next stage's gmem while MMAs run
        ldg_stage(s + 1 <= last ? s + 1 : last);

        // ---- ldmatrix + 48 mma (Ahi*Bhi, Alo*Bhi, then Ahi*Blo) ----
        const uint32_t base = smu + (uint32_t)buf * BUF_BYTES;
        uint32_t Ah[2][4], Al[2][4], Bf[4][4];
        #pragma unroll
        for (int p = 0; p < 4; p++)
            ldsm4(Bf[p], base + (uint32_t)(OBHI + (wn + p * 16 + brow) * RST + bkh) * 2);
        #pragma unroll
        for (int t = 0; t < 2; t++)
            ldsm4(Ah[t], base + (uint32_t)(OAHI + (wm + t * 16 + arow) * RST + akh) * 2);
        #pragma unroll
        for (int t = 0; t < 2; t++)
            ldsm4(Al[t], base + (uint32_t)(OALO + (wm + t * 16 + arow) * RST + akh) * 2);
        #pragma unroll
        for (int t = 0; t < 2; t++)
            #pragma unroll
            for (int p = 0; p < 4; p++) {
                mma16816(acc[t][p * 2 + 0], Ah[t], &Bf[p][0]);
                mma16816(acc[t][p * 2 + 1], Ah[t], &Bf[p][2]);
                mma16816(acc[t][p * 2 + 0], Al[t], &Bf[p][0]);
                mma16816(acc[t][p * 2 + 1], Al[t], &Bf[p][2]);
            }
        // reload B-lo into the same fragment registers, then Ahi*Blo
        #pragma unroll
        for (int p = 0; p < 4; p++)
            ldsm4(Bf[p], base + (uint32_t)(OBLO + (wn + p * 16 + brow) * RST + bkh) * 2);
        #pragma unroll
        for (int t = 0; t < 2; t++)
            #pragma unroll
            for (int p = 0; p < 4; p++) {
                mma16816(acc[t][p * 2 + 0], Ah[t], &Bf[p][0]);
                mma16816(acc[t][p * 2 + 1], Ah[t], &Bf[p][2]);
            }
        __syncthreads();
    }

    // ---- epilogue: write split-K partials ----
    float* part = g_part + (size_t)z * (512 * 256);
    #pragma unroll
    for (int t = 0; t < 2; t++) {
        int mr = m0 + wm + t * 16 + (lane >> 2);
        #pragma unroll
        for (int p8 = 0; p8 < 8; p8++) {
            int nc = n0 + wn + p8 * 8 + (lane & 3) * 2;
            *(float2*)(part + (size_t)mr * 256 + nc) =
                make_float2(acc[t][p8][0], acc[t][p8][1]);
            *(float2*)(part + (size_t)(mr + 8) * 256 + nc) =
                make_float2(acc[t][p8][2], acc[t][p8][3]);
        }
    }
}

// ---------------------------------------------------------------------------
// MLP layer: C = relu(A @ W^T + bias)   (fp32 SIMT)
// ---------------------------------------------------------------------------
__global__ __launch_bounds__(256) void mlp_layer_kernel(
    const float* __restrict__ A, const float* __restrict__ W,
    const float* __restrict__ bias, float* __restrict__ C,
    int M, int N, int K)
{
    __shared__ float a_s[16][68];
    __shared__ float w_s[16][68];
    int m0 = blockIdx.y * 64, n0 = blockIdx.x * 64;
    int tid = threadIdx.x;
    int tx = tid & 15, ty = tid >> 4;
    int lrow = tid >> 2, lk = (tid & 3) * 4;
    float acc[4][4] = {};

    for (int k0 = 0; k0 < K; k0 += 16) {
        float4 av = *(const float4*)(A + (size_t)(m0 + lrow) * K + k0 + lk);
        float4 wv = *(const float4*)(W + (size_t)(n0 + lrow) * K + k0 + lk);
        a_s[lk + 0][lrow] = av.x; a_s[lk + 1][lrow] = av.y;
        a_s[lk + 2][lrow] = av.z; a_s[lk + 3][lrow] = av.w;
        w_s[lk + 0][lrow] = wv.x; w_s[lk + 1][lrow] = wv.y;
        w_s[lk + 2][lrow] = wv.z; w_s[lk + 3][lrow] = wv.w;
        __syncthreads();
        #pragma unroll
        for (int kk = 0; kk < 16; kk++) {
            float4 ra = *(const float4*)&a_s[kk][ty * 4];
            float4 rb = *(const float4*)&w_s[kk][tx * 4];
            float ar[4] = {ra.x, ra.y, ra.z, ra.w};
            float br[4] = {rb.x, rb.y, rb.z, rb.w};
            #pragma unroll
            for (int i = 0; i < 4; i++)
                #pragma unroll
                for (int j = 0; j < 4; j++)
                    acc[i][j] += ar[i] * br[j];
        }
        __syncthreads();
    }
    #pragma unroll
    for (int i = 0; i < 4; i++) {
        int m = m0 + ty * 4 + i;
        #pragma unroll
        for (int j = 0; j < 4; j++) {
            int n = n0 + tx * 4 + j;
            float v = acc[i][j] + bias[n];
            C[(size_t)m * N + n] = v > 0.f ? v : 0.f;
        }
    }
}

// ---------------------------------------------------------------------------
// out[b,o] = b_b[o] + sum_z part[z][b,o] + sum_d iv[b,d]*b_d[d*256+o]
// ---------------------------------------------------------------------------
__global__ __launch_bounds__(256) void reduce_kernel(
    const float* __restrict__ iv, const float* __restrict__ bd,
    const float* __restrict__ bb, float* __restrict__ out)
{
    __shared__ float sIv[256];
    int b = blockIdx.x;
    int o = threadIdx.x;
    sIv[o] = iv[(size_t)b * 256 + o];
    __syncthreads();
    size_t idx = (size_t)b * 256 + o;
    float s = bb[o];
    #pragma unroll 8
    for (int z = 0; z < 32; z++)
        s += g_part[(size_t)z * 131072 + idx];
    #pragma unroll 8
    for (int d = 0; d < 256; d++)
        s = fmaf(sIv[d], bd[d * 256 + o], s);
    out[idx] = s;
}

extern "C" void kernel_launch(void* const* d_in, const int* in_sizes, int n_in,
                              void* d_out, int out_size)
{
    const float* IV = (const float*)d_in[0];   // input_values [512,256]
    const float* NF = (const float*)d_in[1];   // nan_flag     [512,256]
    int base = (in_sizes[2] == 512 * 256) ? 2 : 3;   // skip `training` if present
    const float* W_in = (const float*)d_in[base + 0];  // [512,256]
    const float* b_in = (const float*)d_in[base + 1];  // [512]
    const float* W_h1 = (const float*)d_in[base + 2];  // [1024,512]
    const float* b_h1 = (const float*)d_in[base + 3];  // [1024]
    const float* W_h2 = (const float*)d_in[base + 4];  // [1024,1024]
    const float* b_h2 = (const float*)d_in[base + 5];  // [1024]
    const float* W_d  = (const float*)d_in[base + 6];  // [65536,1024]
    const float* b_d  = (const float*)d_in[base + 7];  // [65536]
    const float* W_b  = (const float*)d_in[base + 8];  // [256,1024]
    const float* b_b  = (const float*)d_in[base + 9];  // [256]
    float* out = (float*)d_out;

    float *x1, *x2, *x3;
    cudaGetSymbolAddress((void**)&x1, g_x1);
    cudaGetSymbolAddress((void**)&x2, g_x2);
    cudaGetSymbolAddress((void**)&x3, g_x3);

    // MLP
    mlp_layer_kernel<<<dim3(8, 8), 256>>>(NF, W_in, b_in, x1, 512, 512, 256);
    mlp_layer_kernel<<<dim3(16, 8), 256>>>(x1, W_h1, b_h1, x2, 512, 1024, 512);
    mlp_layer_kernel<<<dim3(16, 8), 256>>>(x2, W_h2, b_h2, x3, 512, 1024, 1024);

    // Main contraction (+ W_b fold at z==0), 2 CTAs/SM
    main_mma_kernel<<<dim3(4, 2, 32), 256>>>(IV, W_d, W_b, x3);

    // Deterministic split-K reduce + bias terms
    reduce_kernel<<<dim3(512), 256>>>(IV, b_d, b_b, out);
}

// round 16
// speedup vs baseline: 1.2560x; 1.0240x over previous
#include <cuda_runtime.h>
#include <cuda_bf16.h>
#include <cstdint>

#define DINL __device__ __forceinline__

// B=512, D=256, O=256, H=[512,1024,1024]
// out[b,o] = b_b[o] + sum_h x3[b,h]*W_b[o,h] + sum_d iv[b,d]*b_d[d*256+o]
//          + sum_{d,h} iv[b,d]*x3[b,h]*W_d[d*256+o, h]
// Main + comp_b via bf16 mma.sync (hi/lo 3-GEMM split), split-K over d.
// Main kernel = exact R6 config (best measured). MLP also on MMA now.

__device__ float g_x1[512 * 512];
__device__ float g_x2[512 * 1024];
__device__ float g_x3[512 * 1024];
__device__ float g_part[32 * 512 * 256];   // split-K partials [z][b][o]

DINL uint32_t s2u(const void* p) {
    uint32_t a;
    asm("{ .reg .u64 t; cvta.to.shared.u64 t, %1; cvt.u32.u64 %0, t; }"
        : "=r"(a) : "l"(p));
    return a;
}
// pack: low half = bf16(e0), high half = bf16(e1)
DINL uint32_t bfpack(float e0, float e1) {
    uint32_t r;
    asm("cvt.rn.bf16x2.f32 %0, %1, %2;" : "=r"(r) : "f"(e1), "f"(e0));
    return r;
}
DINL void ldsm4(uint32_t* r, uint32_t a) {
    asm volatile("ldmatrix.sync.aligned.m8n8.x4.shared.b16 {%0,%1,%2,%3}, [%4];"
                 : "=r"(r[0]), "=r"(r[1]), "=r"(r[2]), "=r"(r[3]) : "r"(a));
}
DINL void mma16816(float* c, const uint32_t* a, const uint32_t* b) {
    asm volatile(
        "mma.sync.aligned.m16n8k16.row.col.f32.bf16.bf16.f32 "
        "{%0,%1,%2,%3}, {%4,%5,%6,%7}, {%8,%9}, {%0,%1,%2,%3};"
        : "+f"(c[0]), "+f"(c[1]), "+f"(c[2]), "+f"(c[3])
        : "r"(a[0]), "r"(a[1]), "r"(a[2]), "r"(a[3]), "r"(b[0]), "r"(b[1]));
}
// split 8 fp32 -> bf16 hi (uint4) + bf16 lo residual (uint4)
DINL void split8(float4 f0, float4 f1, uint4& hi, uint4& lo) {
    hi.x = bfpack(f0.x, f0.y); hi.y = bfpack(f0.z, f0.w);
    hi.z = bfpack(f1.x, f1.y); hi.w = bfpack(f1.z, f1.w);
    lo.x = bfpack(f0.x - __uint_as_float(hi.x << 16),
                  f0.y - __uint_as_float(hi.x & 0xFFFF0000u));
    lo.y = bfpack(f0.z - __uint_as_float(hi.y << 16),
                  f0.w - __uint_as_float(hi.y & 0xFFFF0000u));
    lo.z = bfpack(f1.x - __uint_as_float(hi.z << 16),
                  f1.y - __uint_as_float(hi.z & 0xFFFF0000u));
    lo.w = bfpack(f1.z - __uint_as_float(hi.w << 16),
                  f1.w - __uint_as_float(hi.w & 0xFFFF0000u));
}

// ======================= MAIN KERNEL (exact R6 config) ======================
// smem layout (elements of bf16), row stride 24 (48B: ldmatrix conflict-free)
static constexpr int AS = 128 * 24;              // A tile (128 rows x 16 k)
static constexpr int BS = 256 * 24;              // B tile (256 rows x 16 k)
static constexpr int BUF_EL = 2 * AS + 2 * BS;   // Ahi|Alo|Bhi|Blo = 18432 el
static constexpr int OAHI = 0, OALO = AS, OBHI = 2 * AS, OBLO = 2 * AS + BS;
static constexpr int DSMEM_BYTES = 2 * BUF_EL * 2;   // 73728 B

// Grid (m=4, z=32), 512 threads. CTA tile 128x256; K = 8*1024 (+Wb at z==0).
__global__ __launch_bounds__(512) void main_mma_kernel(
    const float* __restrict__ iv, const float* __restrict__ Wd,
    const float* __restrict__ Wb, const float* __restrict__ x3)
{
    extern __shared__ __align__(16) __nv_bfloat16 sm[];
    const int tid = threadIdx.x, lane = tid & 31, wid = tid >> 5;
    const int m0 = blockIdx.x * 128, z = blockIdx.y;
    const int wm = (wid & 1) * 64, wn = (wid >> 1) * 32;
    const int nst = (z == 0) ? 9 * 64 : 8 * 64;

    const int rowA = tid >> 2, k4 = (tid & 3) * 4;
    const int rowB = tid >> 1, k8 = (tid & 1) * 8;

    float acc[4][4][4] = {};

    float4 aF, b0F, b1F;
    float ivv;
    auto ldg_stage = [&](int s) {
        int g = s >> 6, h0 = (s & 63) * 16;
        const float* Wbase = (g < 8) ? (Wd + ((size_t)((z * 8 + g) * 256)) * 1024) : Wb;
        ivv = (g < 8) ? __ldg(iv + (size_t)(m0 + rowA) * 256 + (z * 8 + g)) : 1.0f;
        aF = *(const float4*)(x3 + (size_t)(m0 + rowA) * 1024 + h0 + k4);
        const float* wp = Wbase + (size_t)rowB * 1024 + h0 + k8;
        b0F = *(const float4*)(wp);
        b1F = *(const float4*)(wp + 4);
    };
    ldg_stage(0);

    const uint32_t smu = s2u(sm);
    const int arow = (lane & 7) + ((lane >> 3) & 1) * 8;
    const int akh = ((lane >> 4) & 1) * 8;
    const int brow = (lane & 7) + ((lane >> 4) & 1) * 8;
    const int bkh = ((lane >> 3) & 1) * 8;

    for (int s = 0; s < nst; ++s) {
        const int buf = s & 1;
        __nv_bfloat16* bp = sm + buf * BUF_EL;

        // ---- convert + STS stage s (A = iv*x3; hi/lo bf16 split) ----
        {
            float fx = aF.x * ivv, fy = aF.y * ivv, fz = aF.z * ivv, fw = aF.w * ivv;
            uint32_t h01 = bfpack(fx, fy), h23 = bfpack(fz, fw);
            float hx = __uint_as_float(h01 << 16);
            float hy = __uint_as_float(h01 & 0xFFFF0000u);
            float hz = __uint_as_float(h23 << 16);
            float hw = __uint_as_float(h23 & 0xFFFF0000u);
            uint32_t l01 = bfpack(fx - hx, fy - hy), l23 = bfpack(fz - hz, fw - hw);
            *(uint2*)(bp + OAHI + rowA * 24 + k4) = make_uint2(h01, h23);
            *(uint2*)(bp + OALO + rowA * 24 + k4) = make_uint2(l01, l23);

            uint32_t p01 = bfpack(b0F.x, b0F.y), p23 = bfpack(b0F.z, b0F.w);
            float px = __uint_as_float(p01 << 16);
            float py = __uint_as_float(p01 & 0xFFFF0000u);
            float pz = __uint_as_float(p23 << 16);
            float pw = __uint_as_float(p23 & 0xFFFF0000u);
            uint32_t q01 = bfpack(b0F.x - px, b0F.y - py);
            uint32_t q23 = bfpack(b0F.z - pz, b0F.w - pw);
            *(uint2*)(bp + OBHI + rowB * 24 + k8) = make_uint2(p01, p23);
            *(uint2*)(bp + OBLO + rowB * 24 + k8) = make_uint2(q01, q23);

            uint32_t r01 = bfpack(b1F.x, b1F.y), r23 = bfpack(b1F.z, b1F.w);
            float rx = __uint_as_float(r01 << 16);
            float ry = __uint_as_float(r01 & 0xFFFF0000u);
            float rz = __uint_as_float(r23 << 16);
            float rw = __uint_as_float(r23 & 0xFFFF0000u);
            uint32_t s01 = bfpack(b1F.x - rx, b1F.y - ry);
            uint32_t s23 = bfpack(b1F.z - rz, b1F.w - rw);
            *(uint2*)(bp + OBHI + rowB * 24 + k8 + 4) = make_uint2(r01, r23);
            *(uint2*)(bp + OBLO + rowB * 24 + k8 + 4) = make_uint2(s01, s23);
        }
        __syncthreads();

        // prefetch next stage's gmem while MMAs run
        if (s + 1 < nst) ldg_stage(s + 1);

        // ---- ldmatrix + 48 mma (Ahi*Bhi, Ahi*Blo, Alo*Bhi) ----
        const uint32_t base = smu + (uint32_t)buf * (BUF_EL * 2);
        uint32_t Ah[4][4], Bh[2][4], Bl[2][4];
        #pragma unroll
        for (int t = 0; t < 4; t++)
            ldsm4(Ah[t], base + (uint32_t)(OAHI + (wm + t * 16 + arow) * 24 + akh) * 2);
        #pragma unroll
        for (int p = 0; p < 2; p++) {
            ldsm4(Bh[p], base + (uint32_t)(OBHI + (wn + p * 16 + brow) * 24 + bkh) * 2);
            ldsm4(Bl[p], base + (uint32_t)(OBLO + (wn + p * 16 + brow) * 24 + bkh) * 2);
        }
        #pragma unroll
        for (int mi = 0; mi < 4; mi++)
            #pragma unroll
            for (int ni = 0; ni < 4; ni++) {
                mma16816(acc[mi][ni], Ah[mi], &Bh[ni >> 1][(ni & 1) * 2]);
                mma16816(acc[mi][ni], Ah[mi], &Bl[ni >> 1][(ni & 1) * 2]);
            }
        uint32_t Al[4][4];
        #pragma unroll
        for (int t = 0; t < 4; t++)
            ldsm4(Al[t], base + (uint32_t)(OALO + (wm + t * 16 + arow) * 24 + akh) * 2);
        #pragma unroll
        for (int mi = 0; mi < 4; mi++)
            #pragma unroll
            for (int ni = 0; ni < 4; ni++)
                mma16816(acc[mi][ni], Al[mi], &Bh[ni >> 1][(ni & 1) * 2]);

        __syncthreads();
    }

    float* part = g_part + (size_t)z * (512 * 256);
    #pragma unroll
    for (int mi = 0; mi < 4; mi++) {
        int mr = m0 + wm + mi * 16 + (lane >> 2);
        #pragma unroll
        for (int ni = 0; ni < 4; ni++) {
            int nc = wn + ni * 8 + (lane & 3) * 2;
            *(float2*)(part + (size_t)mr * 256 + nc) =
                make_float2(acc[mi][ni][0], acc[mi][ni][1]);
            *(float2*)(part + (size_t)(mr + 8) * 256 + nc) =
                make_float2(acc[mi][ni][2], acc[mi][ni][3]);
        }
    }
}

// ======================= MLP on MMA =========================================
// C[512,N] = relu(A[512,K] @ W[N,K]^T + bias). CTA tile 64x64, 256 threads,
// 8 warps (warp tile 16x32), bf16 hi/lo 3-term split, double-buffered.
static constexpr int MTS = 64 * 24;              // 1536 el per tile
static constexpr int MOAHI = 0, MOALO = MTS, MOBHI = 2 * MTS, MOBLO = 3 * MTS;
static constexpr int MBUF_EL = 4 * MTS;          // 6144 el (12 KB per buffer)

__global__ __launch_bounds__(256, 2) void mlp_mma_kernel(
    const float* __restrict__ A, const float* __restrict__ W,
    const float* __restrict__ bias, float* __restrict__ C,
    int N, int K)
{
    __shared__ __align__(16) __nv_bfloat16 sm[2][MBUF_EL];

    const int tid = threadIdx.x, lane = tid & 31, wid = tid >> 5;
    const int m0 = blockIdx.y * 64, n0 = blockIdx.x * 64;
    const int wm = (wid >> 1) * 16, wn = (wid & 1) * 32;
    const int nst = K >> 4;

    // loader: threads 0-127 -> A rows, 128-255 -> W rows (2 thr/row, 8 el)
    const bool isA = tid < 128;
    const int lrow = (tid & 127) >> 1, lk8 = (tid & 1) * 8;
    const float* src = isA ? (A + (size_t)(m0 + lrow) * K + lk8)
                           : (W + (size_t)(n0 + lrow) * K + lk8);
    const int ohi = isA ? MOAHI : MOBHI;
    const int olo = isA ? MOALO : MOBLO;
    const int rowoff = lrow * 24 + lk8;

    float4 f0, f1;
    auto ldg_stage = [&](int s) {
        const float* p = src + (size_t)s * 16;
        f0 = *(const float4*)p; f1 = *(const float4*)(p + 4);
    };
    ldg_stage(0);

    const uint32_t smu = s2u(sm);
    const int arow = (lane & 7) + ((lane >> 3) & 1) * 8;
    const int akh = ((lane >> 4) & 1) * 8;
    const int brow = (lane & 7) + ((lane >> 4) & 1) * 8;
    const int bkh = ((lane >> 3) & 1) * 8;

    const uint32_t aoh = (uint32_t)(MOAHI + (wm + arow) * 24 + akh) * 2;
    const uint32_t aol = (uint32_t)(MOALO + (wm + arow) * 24 + akh) * 2;
    uint32_t boh[2], bol[2];
    #pragma unroll
    for (int p = 0; p < 2; p++) {
        boh[p] = (uint32_t)(MOBHI + (wn + p * 16 + brow) * 24 + bkh) * 2;
        bol[p] = (uint32_t)(MOBLO + (wn + p * 16 + brow) * 24 + bkh) * 2;
    }

    float acc[4][4] = {};   // 4 n8 frags
    for (int s = 0; s < nst; ++s) {
        const int buf = s & 1;
        {
            uint4 hi, lo;
            split8(f0, f1, hi, lo);
            __nv_bfloat16* bp = sm[buf];
            *(uint4*)(bp + ohi + rowoff) = hi;
            *(uint4*)(bp + olo + rowoff) = lo;
        }
        __syncthreads();
        if (s + 1 < nst) ldg_stage(s + 1);

        const uint32_t base = smu + (uint32_t)buf * (MBUF_EL * 2);
        uint32_t Ah[4], Al[4], Bh[2][4], Bl[2][4];
        ldsm4(Ah, base + aoh);
        ldsm4(Al, base + aol);
        #pragma unroll
        for (int p = 0; p < 2; p++) {
            ldsm4(Bh[p], base + boh[p]);
            ldsm4(Bl[p], base + bol[p]);
        }
        #pragma unroll
        for (int f = 0; f < 4; f++) {
            mma16816(acc[f], Ah, &Bh[f >> 1][(f & 1) * 2]);
            mma16816(acc[f], Al, &Bh[f >> 1][(f & 1) * 2]);
            mma16816(acc[f], Ah, &Bl[f >> 1][(f & 1) * 2]);
        }
        __syncthreads();
    }

    // epilogue: bias + relu, fp32 store
    const int mr = m0 + wm + (lane >> 2);
    #pragma unroll
    for (int f = 0; f < 4; f++) {
        int nc = n0 + wn + f * 8 + (lane & 3) * 2;
        float b0 = bias[nc], b1 = bias[nc + 1];
        float c0 = fmaxf(acc[f][0] + b0, 0.f), c1 = fmaxf(acc[f][1] + b1, 0.f);
        float c2 = fmaxf(acc[f][2] + b0, 0.f), c3 = fmaxf(acc[f][3] + b1, 0.f);
        *(float2*)(C + (size_t)mr * N + nc) = make_float2(c0, c1);
        *(float2*)(C + (size_t)(mr + 8) * N + nc) = make_float2(c2, c3);
    }
}

// ---------------------------------------------------------------------------
// out[b,o] = b_b[o] + sum_z part[z][b,o] + sum_d iv[b,d]*b_d[d*256+o]
// ---------------------------------------------------------------------------
__global__ __launch_bounds__(256) void reduce_kernel(
    const float* __restrict__ iv, const float* __restrict__ bd,
    const float* __restrict__ bb, float* __restrict__ out)
{
    __shared__ float sIv[256];
    int b = blockIdx.x;
    int o = threadIdx.x;
    sIv[o] = iv[(size_t)b * 256 + o];
    __syncthreads();
    size_t idx = (size_t)b * 256 + o;
    float s = bb[o];
    #pragma unroll 8
    for (int z = 0; z < 32; z++)
        s += g_part[(size_t)z * 131072 + idx];
    #pragma unroll 8
    for (int d = 0; d < 256; d++)
        s = fmaf(sIv[d], bd[d * 256 + o], s);
    out[idx] = s;
}

extern "C" void kernel_launch(void* const* d_in, const int* in_sizes, int n_in,
                              void* d_out, int out_size)
{
    const float* IV = (const float*)d_in[0];   // input_values [512,256]
    const float* NF = (const float*)d_in[1];   // nan_flag     [512,256]
    int base = (in_sizes[2] == 512 * 256) ? 2 : 3;   // skip `training` if present
    const float* W_in = (const float*)d_in[base + 0];  // [512,256]
    const float* b_in = (const float*)d_in[base + 1];  // [512]
    const float* W_h1 = (const float*)d_in[base + 2];  // [1024,512]
    const float* b_h1 = (const float*)d_in[base + 3];  // [1024]
    const float* W_h2 = (const float*)d_in[base + 4];  // [1024,1024]
    const float* b_h2 = (const float*)d_in[base + 5];  // [1024]
    const float* W_d  = (const float*)d_in[base + 6];  // [65536,1024]
    const float* b_d  = (const float*)d_in[base + 7];  // [65536]
    const float* W_b  = (const float*)d_in[base + 8];  // [256,1024]
    const float* b_b  = (const float*)d_in[base + 9];  // [256]
    float* out = (float*)d_out;

    float *x1, *x2, *x3;
    cudaGetSymbolAddress((void**)&x1, g_x1);
    cudaGetSymbolAddress((void**)&x2, g_x2);
    cudaGetSymbolAddress((void**)&x3, g_x3);

    cudaFuncSetAttribute(main_mma_kernel,
                         cudaFuncAttributeMaxDynamicSharedMemorySize, DSMEM_BYTES);

    // MLP on tensor cores
    mlp_mma_kernel<<<dim3(8, 8), 256>>>(NF, W_in, b_in, x1, 512, 256);
    mlp_mma_kernel<<<dim3(16, 8), 256>>>(x1, W_h1, b_h1, x2, 1024, 512);
    mlp_mma_kernel<<<dim3(16, 8), 256>>>(x2, W_h2, b_h2, x3, 1024, 1024);

    // Main contraction (+ W_b fold at z==0) — exact R6 config
    main_mma_kernel<<<dim3(4, 32), 512, DSMEM_BYTES>>>(IV, W_d, W_b, x3);

    // Deterministic split-K reduce + bias terms
    reduce_kernel<<<dim3(512), 256>>>(IV, b_d, b_b, out);
}

// round 17
// speedup vs baseline: 1.6699x; 1.3296x over previous
#include <cuda_runtime.h>
#include <cuda_bf16.h>
#include <cstdint>

#define DINL __device__ __forceinline__

// B=512, D=256, O=256, H=[512,1024,1024]
// out[b,o] = b_b[o] + sum_h x3[b,h]*W_b[o,h] + sum_d iv[b,d]*b_d[d*256+o]
//          + sum_{d,h} iv[b,d]*x3[b,h]*W_d[d*256+o, h]
// Main + comp_b via bf16 mma.sync (hi/lo 3-GEMM split).
// K treated as 257 units (256 d's + 1 Wb); split over 37 chunks so grid
// (4 m x 37 z) = 148 CTAs = one CTA per SM, balanced critical path.

static constexpr int NZ = 37;                  // K-split chunks (257 units)
__device__ float g_x1[512 * 512];
__device__ float g_x2[512 * 1024];
__device__ float g_x3[512 * 1024];
__device__ float g_part[NZ * 512 * 256];       // split-K partials [z][b][o]

DINL uint32_t s2u(const void* p) {
    uint32_t a;
    asm("{ .reg .u64 t; cvta.to.shared.u64 t, %1; cvt.u32.u64 %0, t; }"
        : "=r"(a) : "l"(p));
    return a;
}
// pack: low half = bf16(e0), high half = bf16(e1)
DINL uint32_t bfpack(float e0, float e1) {
    uint32_t r;
    asm("cvt.rn.bf16x2.f32 %0, %1, %2;" : "=r"(r) : "f"(e1), "f"(e0));
    return r;
}
DINL void ldsm4(uint32_t* r, uint32_t a) {
    asm volatile("ldmatrix.sync.aligned.m8n8.x4.shared.b16 {%0,%1,%2,%3}, [%4];"
                 : "=r"(r[0]), "=r"(r[1]), "=r"(r[2]), "=r"(r[3]) : "r"(a));
}
DINL void mma16816(float* c, const uint32_t* a, const uint32_t* b) {
    asm volatile(
        "mma.sync.aligned.m16n8k16.row.col.f32.bf16.bf16.f32 "
        "{%0,%1,%2,%3}, {%4,%5,%6,%7}, {%8,%9}, {%0,%1,%2,%3};"
        : "+f"(c[0]), "+f"(c[1]), "+f"(c[2]), "+f"(c[3])
        : "r"(a[0]), "r"(a[1]), "r"(a[2]), "r"(a[3]), "r"(b[0]), "r"(b[1]));
}
// split 8 fp32 -> bf16 hi (uint4) + bf16 lo residual (uint4)
DINL void split8(float4 f0, float4 f1, uint4& hi, uint4& lo) {
    hi.x = bfpack(f0.x, f0.y); hi.y = bfpack(f0.z, f0.w);
    hi.z = bfpack(f1.x, f1.y); hi.w = bfpack(f1.z, f1.w);
    lo.x = bfpack(f0.x - __uint_as_float(hi.x << 16),
                  f0.y - __uint_as_float(hi.x & 0xFFFF0000u));
    lo.y = bfpack(f0.z - __uint_as_float(hi.y << 16),
                  f0.w - __uint_as_float(hi.y & 0xFFFF0000u));
    lo.z = bfpack(f1.x - __uint_as_float(hi.z << 16),
                  f1.y - __uint_as_float(hi.z & 0xFFFF0000u));
    lo.w = bfpack(f1.z - __uint_as_float(hi.w << 16),
                  f1.w - __uint_as_float(hi.w & 0xFFFF0000u));
}

// ======================= MAIN KERNEL (R6 body, rebalanced grid) =============
// smem layout (elements of bf16), row stride 24 (48B: ldmatrix conflict-free)
static constexpr int AS = 128 * 24;              // A tile (128 rows x 16 k)
static constexpr int BS = 256 * 24;              // B tile (256 rows x 16 k)
static constexpr int BUF_EL = 2 * AS + 2 * BS;   // Ahi|Alo|Bhi|Blo = 18432 el
static constexpr int OAHI = 0, OALO = AS, OBHI = 2 * AS, OBLO = 2 * AS + BS;
static constexpr int DSMEM_BYTES = 2 * BUF_EL * 2;   // 73728 B

// Grid (m=4, z=37), 512 threads. CTA tile 128x256; 6-7 K-units per CTA.
__global__ __launch_bounds__(512) void main_mma_kernel(
    const float* __restrict__ iv, const float* __restrict__ Wd,
    const float* __restrict__ Wb, const float* __restrict__ x3)
{
    extern __shared__ __align__(16) __nv_bfloat16 sm[];
    const int tid = threadIdx.x, lane = tid & 31, wid = tid >> 5;
    const int m0 = blockIdx.x * 128, zi = blockIdx.y;
    const int wm = (wid & 1) * 64, wn = (wid >> 1) * 32;
    const int ustart = (257 * zi) / NZ;
    const int uend = (257 * (zi + 1)) / NZ;
    const int nst = (uend - ustart) * 64;

    const int rowA = tid >> 2, k4 = (tid & 3) * 4;
    const int rowB = tid >> 1, k8 = (tid & 1) * 8;

    float acc[4][4][4] = {};

    float4 aF, b0F, b1F;
    float ivv;
    auto ldg_stage = [&](int s) {
        int u = ustart + (s >> 6), h0 = (s & 63) * 16;
        const float* Wbase = (u < 256) ? (Wd + (size_t)u * 256 * 1024) : Wb;
        ivv = (u < 256) ? __ldg(iv + (size_t)(m0 + rowA) * 256 + u) : 1.0f;
        aF = *(const float4*)(x3 + (size_t)(m0 + rowA) * 1024 + h0 + k4);
        const float* wp = Wbase + (size_t)rowB * 1024 + h0 + k8;
        b0F = *(const float4*)(wp);
        b1F = *(const float4*)(wp + 4);
    };
    ldg_stage(0);

    const uint32_t smu = s2u(sm);
    const int arow = (lane & 7) + ((lane >> 3) & 1) * 8;
    const int akh = ((lane >> 4) & 1) * 8;
    const int brow = (lane & 7) + ((lane >> 4) & 1) * 8;
    const int bkh = ((lane >> 3) & 1) * 8;

    for (int s = 0; s < nst; ++s) {
        const int buf = s & 1;
        __nv_bfloat16* bp = sm + buf * BUF_EL;

        // ---- convert + STS stage s (A = iv*x3; hi/lo bf16 split) ----
        {
            float fx = aF.x * ivv, fy = aF.y * ivv, fz = aF.z * ivv, fw = aF.w * ivv;
            uint32_t h01 = bfpack(fx, fy), h23 = bfpack(fz, fw);
            float hx = __uint_as_float(h01 << 16);
            float hy = __uint_as_float(h01 & 0xFFFF0000u);
            float hz = __uint_as_float(h23 << 16);
            float hw = __uint_as_float(h23 & 0xFFFF0000u);
            uint32_t l01 = bfpack(fx - hx, fy - hy), l23 = bfpack(fz - hz, fw - hw);
            *(uint2*)(bp + OAHI + rowA * 24 + k4) = make_uint2(h01, h23);
            *(uint2*)(bp + OALO + rowA * 24 + k4) = make_uint2(l01, l23);

            uint32_t p01 = bfpack(b0F.x, b0F.y), p23 = bfpack(b0F.z, b0F.w);
            float px = __uint_as_float(p01 << 16);
            float py = __uint_as_float(p01 & 0xFFFF0000u);
            float pz = __uint_as_float(p23 << 16);
            float pw = __uint_as_float(p23 & 0xFFFF0000u);
            uint32_t q01 = bfpack(b0F.x - px, b0F.y - py);
            uint32_t q23 = bfpack(b0F.z - pz, b0F.w - pw);
            *(uint2*)(bp + OBHI + rowB * 24 + k8) = make_uint2(p01, p23);
            *(uint2*)(bp + OBLO + rowB * 24 + k8) = make_uint2(q01, q23);

            uint32_t r01 = bfpack(b1F.x, b1F.y), r23 = bfpack(b1F.z, b1F.w);
            float rx = __uint_as_float(r01 << 16);
            float ry = __uint_as_float(r01 & 0xFFFF0000u);
            float rz = __uint_as_float(r23 << 16);
            float rw = __uint_as_float(r23 & 0xFFFF0000u);
            uint32_t s01 = bfpack(b1F.x - rx, b1F.y - ry);
            uint32_t s23 = bfpack(b1F.z - rz, b1F.w - rw);
            *(uint2*)(bp + OBHI + rowB * 24 + k8 + 4) = make_uint2(r01, r23);
            *(uint2*)(bp + OBLO + rowB * 24 + k8 + 4) = make_uint2(s01, s23);
        }
        __syncthreads();

        // prefetch next stage's gmem while MMAs run
        if (s + 1 < nst) ldg_stage(s + 1);

        // ---- ldmatrix + 48 mma (Ahi*Bhi, Ahi*Blo, Alo*Bhi) ----
        const uint32_t base = smu + (uint32_t)buf * (BUF_EL * 2);
        uint32_t Ah[4][4], Bh[2][4], Bl[2][4];
        #pragma unroll
        for (int t = 0; t < 4; t++)
            ldsm4(Ah[t], base + (uint32_t)(OAHI + (wm + t * 16 + arow) * 24 + akh) * 2);
        #pragma unroll
        for (int p = 0; p < 2; p++) {
            ldsm4(Bh[p], base + (uint32_t)(OBHI + (wn + p * 16 + brow) * 24 + bkh) * 2);
            ldsm4(Bl[p], base + (uint32_t)(OBLO + (wn + p * 16 + brow) * 24 + bkh) * 2);
        }
        #pragma unroll
        for (int mi = 0; mi < 4; mi++)
            #pragma unroll
            for (int ni = 0; ni < 4; ni++) {
                mma16816(acc[mi][ni], Ah[mi], &Bh[ni >> 1][(ni & 1) * 2]);
                mma16816(acc[mi][ni], Ah[mi], &Bl[ni >> 1][(ni & 1) * 2]);
            }
        uint32_t Al[4][4];
        #pragma unroll
        for (int t = 0; t < 4; t++)
            ldsm4(Al[t], base + (uint32_t)(OALO + (wm + t * 16 + arow) * 24 + akh) * 2);
        #pragma unroll
        for (int mi = 0; mi < 4; mi++)
            #pragma unroll
            for (int ni = 0; ni < 4; ni++)
                mma16816(acc[mi][ni], Al[mi], &Bh[ni >> 1][(ni & 1) * 2]);

        __syncthreads();
    }

    float* part = g_part + (size_t)zi * (512 * 256);
    #pragma unroll
    for (int mi = 0; mi < 4; mi++) {
        int mr = m0 + wm + mi * 16 + (lane >> 2);
        #pragma unroll
        for (int ni = 0; ni < 4; ni++) {
            int nc = wn + ni * 8 + (lane & 3) * 2;
            *(float2*)(part + (size_t)mr * 256 + nc) =
                make_float2(acc[mi][ni][0], acc[mi][ni][1]);
            *(float2*)(part + (size_t)(mr + 8) * 256 + nc) =
                make_float2(acc[mi][ni][2], acc[mi][ni][3]);
        }
    }
}

// ======================= MLP on MMA =========================================
// C[512,N] = relu(A[512,K] @ W[N,K]^T + bias). CTA tile 64x64, 256 threads,
// 8 warps (warp tile 16x32), bf16 hi/lo 3-term split, double-buffered.
static constexpr int MTS = 64 * 24;              // 1536 el per tile
static constexpr int MOAHI = 0, MOALO = MTS, MOBHI = 2 * MTS, MOBLO = 3 * MTS;
static constexpr int MBUF_EL = 4 * MTS;          // 6144 el (12 KB per buffer)

__global__ __launch_bounds__(256, 2) void mlp_mma_kernel(
    const float* __restrict__ A, const float* __restrict__ W,
    const float* __restrict__ bias, float* __restrict__ C,
    int N, int K)
{
    __shared__ __align__(16) __nv_bfloat16 sm[2][MBUF_EL];

    const int tid = threadIdx.x, lane = tid & 31, wid = tid >> 5;
    const int m0 = blockIdx.y * 64, n0 = blockIdx.x * 64;
    const int wm = (wid >> 1) * 16, wn = (wid & 1) * 32;
    const int nst = K >> 4;

    const bool isA = tid < 128;
    const int lrow = (tid & 127) >> 1, lk8 = (tid & 1) * 8;
    const float* src = isA ? (A + (size_t)(m0 + lrow) * K + lk8)
                           : (W + (size_t)(n0 + lrow) * K + lk8);
    const int ohi = isA ? MOAHI : MOBHI;
    const int olo = isA ? MOALO : MOBLO;
    const int rowoff = lrow * 24 + lk8;

    float4 f0, f1;
    auto ldg_stage = [&](int s) {
        const float* p = src + (size_t)s * 16;
        f0 = *(const float4*)p; f1 = *(const float4*)(p + 4);
    };
    ldg_stage(0);

    const uint32_t smu = s2u(sm);
    const int arow = (lane & 7) + ((lane >> 3) & 1) * 8;
    const int akh = ((lane >> 4) & 1) * 8;
    const int brow = (lane & 7) + ((lane >> 4) & 1) * 8;
    const int bkh = ((lane >> 3) & 1) * 8;

    const uint32_t aoh = (uint32_t)(MOAHI + (wm + arow) * 24 + akh) * 2;
    const uint32_t aol = (uint32_t)(MOALO + (wm + arow) * 24 + akh) * 2;
    uint32_t boh[2], bol[2];
    #pragma unroll
    for (int p = 0; p < 2; p++) {
        boh[p] = (uint32_t)(MOBHI + (wn + p * 16 + brow) * 24 + bkh) * 2;
        bol[p] = (uint32_t)(MOBLO + (wn + p * 16 + brow) * 24 + bkh) * 2;
    }

    float acc[4][4] = {};
    for (int s = 0; s < nst; ++s) {
        const int buf = s & 1;
        {
            uint4 hi, lo;
            split8(f0, f1, hi, lo);
            __nv_bfloat16* bp = sm[buf];
            *(uint4*)(bp + ohi + rowoff) = hi;
            *(uint4*)(bp + olo + rowoff) = lo;
        }
        __syncthreads();
        if (s + 1 < nst) ldg_stage(s + 1);

        const uint32_t base = smu + (uint32_t)buf * (MBUF_EL * 2);
        uint32_t Ah[4], Al[4], Bh[2][4], Bl[2][4];
        ldsm4(Ah, base + aoh);
        ldsm4(Al, base + aol);
        #pragma unroll
        for (int p = 0; p < 2; p++) {
            ldsm4(Bh[p], base + boh[p]);
            ldsm4(Bl[p], base + bol[p]);
        }
        #pragma unroll
        for (int f = 0; f < 4; f++) {
            mma16816(acc[f], Ah, &Bh[f >> 1][(f & 1) * 2]);
            mma16816(acc[f], Al, &Bh[f >> 1][(f & 1) * 2]);
            mma16816(acc[f], Ah, &Bl[f >> 1][(f & 1) * 2]);
        }
        __syncthreads();
    }

    const int mr = m0 + wm + (lane >> 2);
    #pragma unroll
    for (int f = 0; f < 4; f++) {
        int nc = n0 + wn + f * 8 + (lane & 3) * 2;
        float b0 = bias[nc], b1 = bias[nc + 1];
        float c0 = fmaxf(acc[f][0] + b0, 0.f), c1 = fmaxf(acc[f][1] + b1, 0.f);
        float c2 = fmaxf(acc[f][2] + b0, 0.f), c3 = fmaxf(acc[f][3] + b1, 0.f);
        *(float2*)(C + (size_t)mr * N + nc) = make_float2(c0, c1);
        *(float2*)(C + (size_t)(mr + 8) * N + nc) = make_float2(c2, c3);
    }
}

// ---------------------------------------------------------------------------
// out[b,o] = b_b[o] + sum_z part[z][b,o] + sum_d iv[b,d]*b_d[d*256+o]
// ---------------------------------------------------------------------------
__global__ __launch_bounds__(256) void reduce_kernel(
    const float* __restrict__ iv, const float* __restrict__ bd,
    const float* __restrict__ bb, float* __restrict__ out)
{
    __shared__ float sIv[256];
    int b = blockIdx.x;
    int o = threadIdx.x;
    sIv[o] = iv[(size_t)b * 256 + o];
    __syncthreads();
    size_t idx = (size_t)b * 256 + o;
    float s = bb[o];
    #pragma unroll
    for (int z = 0; z < NZ; z++)
        s += g_part[(size_t)z * 131072 + idx];
    #pragma unroll 8
    for (int d = 0; d < 256; d++)
        s = fmaf(sIv[d], bd[d * 256 + o], s);
    out[idx] = s;
}

extern "C" void kernel_launch(void* const* d_in, const int* in_sizes, int n_in,
                              void* d_out, int out_size)
{
    const float* IV = (const float*)d_in[0];   // input_values [512,256]
    const float* NF = (const float*)d_in[1];   // nan_flag     [512,256]
    int base = (in_sizes[2] == 512 * 256) ? 2 : 3;   // skip `training` if present
    const float* W_in = (const float*)d_in[base + 0];  // [512,256]
    const float* b_in = (const float*)d_in[base + 1];  // [512]
    const float* W_h1 = (const float*)d_in[base + 2];  // [1024,512]
    const float* b_h1 = (const float*)d_in[base + 3];  // [1024]
    const float* W_h2 = (const float*)d_in[base + 4];  // [1024,1024]
    const float* b_h2 = (const float*)d_in[base + 5];  // [1024]
    const float* W_d  = (const float*)d_in[base + 6];  // [65536,1024]
    const float* b_d  = (const float*)d_in[base + 7];  // [65536]
    const float* W_b  = (const float*)d_in[base + 8];  // [256,1024]
    const float* b_b  = (const float*)d_in[base + 9];  // [256]
    float* out = (float*)d_out;

    float *x1, *x2, *x3;
    cudaGetSymbolAddress((void**)&x1, g_x1);
    cudaGetSymbolAddress((void**)&x2, g_x2);
    cudaGetSymbolAddress((void**)&x3, g_x3);

    cudaFuncSetAttribute(main_mma_kernel,
                         cudaFuncAttributeMaxDynamicSharedMemorySize, DSMEM_BYTES);

    // MLP on tensor cores
    mlp_mma_kernel<<<dim3(8, 8), 256>>>(NF, W_in, b_in, x1, 512, 256);
    mlp_mma_kernel<<<dim3(16, 8), 256>>>(x1, W_h1, b_h1, x2, 1024, 512);
    mlp_mma_kernel<<<dim3(16, 8), 256>>>(x2, W_h2, b_h2, x3, 1024, 1024);

    // Main contraction: 148 CTAs = 1/SM, balanced 257-unit K-split
    main_mma_kernel<<<dim3(4, NZ), 512, DSMEM_BYTES>>>(IV, W_d, W_b, x3);

    // Deterministic split-K reduce + bias terms
    reduce_kernel<<<dim3(512), 256>>>(IV, b_d, b_b, out);
}